// round 2
// baseline (speedup 1.0000x reference)
#include <cuda_runtime.h>
#include <math.h>

// Problem constants
#define B_    64
#define NT    197
#define C_    768
#define H_    12
#define HD    64
#define MROWS (B_ * NT)     // 12608
#define QKVC  (3 * C_)      // 2304

// Scratch (static device globals — no runtime allocation allowed)
__device__ float g_qkv[(size_t)MROWS * QKVC];   // [B*N, 3C]  q|k|v per row
__device__ float g_att[(size_t)MROWS * C_];     // [B*N, C]   attention output

// ---------------------------------------------------------------------------
// SGEMM:  C[m,n] = sum_k A[m,k] * B[n,k] (+ bias[n])
// A: [M,K] row-major, B: [N,K] row-major (i.e. C = A * B^T)
// Tile: BM=64, BN=128, BK=16; 256 threads; 4x8 micro-tile with split-column
// B blocking (cols tx*4 and 64+tx*4) so LDS.128 reads are conflict-free.
// M % 64 == 0, N % 128 == 0, K % 16 == 0 assumed (holds for all 3 uses... 2 uses).
// ---------------------------------------------------------------------------
__global__ void __launch_bounds__(256) sgemm_nt(
    const float* __restrict__ A, const float* __restrict__ Bm,
    const float* __restrict__ bias, float* __restrict__ Cm,
    int M, int N, int K)
{
    __shared__ float As[16][64];
    __shared__ float Bs[16][128];

    const int tid = threadIdx.x;
    const int tx  = tid & 15;          // 0..15 -> N micro-tiles
    const int ty  = tid >> 4;          // 0..15 -> M micro-tiles

    const float* Ab = A  + (size_t)blockIdx.y * 64  * K;
    const float* Bb = Bm + (size_t)blockIdx.x * 128 * K;

    const int lr = tid >> 2;           // 0..63
    const int lc = (tid & 3) * 4;      // 0,4,8,12

    float acc[4][8];
#pragma unroll
    for (int i = 0; i < 4; i++)
#pragma unroll
        for (int j = 0; j < 8; j++) acc[i][j] = 0.f;

    for (int k0 = 0; k0 < K; k0 += 16) {
        float4 av = *(const float4*)(Ab + (size_t)lr * K + k0 + lc);
        float4 b0 = *(const float4*)(Bb + (size_t)lr * K + k0 + lc);
        float4 b1 = *(const float4*)(Bb + (size_t)(lr + 64) * K + k0 + lc);
        As[lc + 0][lr] = av.x; As[lc + 1][lr] = av.y;
        As[lc + 2][lr] = av.z; As[lc + 3][lr] = av.w;
        Bs[lc + 0][lr] = b0.x; Bs[lc + 1][lr] = b0.y;
        Bs[lc + 2][lr] = b0.z; Bs[lc + 3][lr] = b0.w;
        Bs[lc + 0][lr + 64] = b1.x; Bs[lc + 1][lr + 64] = b1.y;
        Bs[lc + 2][lr + 64] = b1.z; Bs[lc + 3][lr + 64] = b1.w;
        __syncthreads();

#pragma unroll
        for (int k = 0; k < 16; k++) {
            float a[4], b[8];
            *(float4*)a       = *(const float4*)&As[k][ty * 4];
            *(float4*)(b)     = *(const float4*)&Bs[k][tx * 4];
            *(float4*)(b + 4) = *(const float4*)&Bs[k][64 + tx * 4];
#pragma unroll
            for (int i = 0; i < 4; i++)
#pragma unroll
                for (int j = 0; j < 8; j++)
                    acc[i][j] += a[i] * b[j];
        }
        __syncthreads();
    }

    const int n0 = blockIdx.x * 128 + tx * 4;        // first col block
    const int n1 = n0 + 64;                          // second col block
    float bb[8];
#pragma unroll
    for (int j = 0; j < 4; j++) {
        bb[j]     = bias ? bias[n0 + j] : 0.f;
        bb[4 + j] = bias ? bias[n1 + j] : 0.f;
    }
#pragma unroll
    for (int i = 0; i < 4; i++) {
        int m = blockIdx.y * 64 + ty * 4 + i;
        float4 o0 = make_float4(acc[i][0] + bb[0], acc[i][1] + bb[1],
                                acc[i][2] + bb[2], acc[i][3] + bb[3]);
        float4 o1 = make_float4(acc[i][4] + bb[4], acc[i][5] + bb[5],
                                acc[i][6] + bb[6], acc[i][7] + bb[7]);
        *(float4*)(Cm + (size_t)m * N + n0) = o0;
        *(float4*)(Cm + (size_t)m * N + n1) = o1;
    }
}

// ---------------------------------------------------------------------------
// Attention: one CTA per (b,h). K/V staged in smem (stride 68 -> conflict-free
// float4 QK / float2 PV). Each warp processes query rows n = warp, warp+8, ...
// Writes attention output to g_att and CLS-row stats (row 0, keys 1..196,
// mean over heads via atomicAdd) to gattn.
// ---------------------------------------------------------------------------
#define KV_STRIDE 68
#define S_STRIDE  200
// floats: K + V + S + Q
#define ATTN_SMEM_FLOATS (2 * NT * KV_STRIDE + 8 * S_STRIDE + 8 * 64)
#define ATTN_SMEM_BYTES  (ATTN_SMEM_FLOATS * 4)

__global__ void __launch_bounds__(256) attn_kernel(
    const float* __restrict__ qkv, float* __restrict__ attn_out,
    float* __restrict__ gattn)
{
    const int b = blockIdx.x / H_;
    const int h = blockIdx.x % H_;

    extern __shared__ float sm[];
    float* K_s = sm;
    float* V_s = K_s + NT * KV_STRIDE;
    float* S   = V_s + NT * KV_STRIDE;   // [8][S_STRIDE]
    float* Qs  = S + 8 * S_STRIDE;       // [8][64]

    const int tid  = threadIdx.x;
    const int lane = tid & 31;
    const int w    = tid >> 5;

    const float* base = qkv + (size_t)b * NT * QKVC + h * HD;

    // Stage K and V tiles
    for (int idx = tid; idx < NT * HD; idx += 256) {
        int m = idx >> 6, e = idx & 63;
        const float* row = base + (size_t)m * QKVC;
        K_s[m * KV_STRIDE + e] = row[C_ + e];          // k at offset 768
        V_s[m * KV_STRIDE + e] = row[2 * C_ + e];      // v at offset 1536
    }
    __syncthreads();

    const float scale = 0.125f;   // hd^-0.5, hd = 64

    for (int n = w; n < NT; n += 8) {
        // Load this query row into the warp's smem slot
        const float* qrow = base + (size_t)n * QKVC;
        Qs[w * 64 + lane]      = qrow[lane];
        Qs[w * 64 + lane + 32] = qrow[lane + 32];
        __syncwarp();

        // Scores: lane handles m = lane + 32*i
        float s[7];
#pragma unroll
        for (int i = 0; i < 7; i++) s[i] = 0.f;
#pragma unroll
        for (int e = 0; e < 64; e += 4) {
            float4 q4 = *(const float4*)&Qs[w * 64 + e];
#pragma unroll
            for (int i = 0; i < 7; i++) {
                int m = lane + 32 * i;
                if (m < NT) {
                    float4 k4 = *(const float4*)&K_s[m * KV_STRIDE + e];
                    s[i] += q4.x * k4.x + q4.y * k4.y + q4.z * k4.z + q4.w * k4.w;
                }
            }
        }
        float mx = -INFINITY;
#pragma unroll
        for (int i = 0; i < 7; i++) {
            int m = lane + 32 * i;
            if (m < NT) { s[i] *= scale; mx = fmaxf(mx, s[i]); }
        }
#pragma unroll
        for (int o = 16; o; o >>= 1)
            mx = fmaxf(mx, __shfl_xor_sync(0xffffffffu, mx, o));

        float sum = 0.f;
#pragma unroll
        for (int i = 0; i < 7; i++) {
            int m = lane + 32 * i;
            if (m < NT) { s[i] = __expf(s[i] - mx); sum += s[i]; }
        }
#pragma unroll
        for (int o = 16; o; o >>= 1)
            sum += __shfl_xor_sync(0xffffffffu, sum, o);
        const float inv = 1.f / sum;

#pragma unroll
        for (int i = 0; i < 7; i++) {
            int m = lane + 32 * i;
            if (m < NT) {
                float p = s[i] * inv;
                S[w * S_STRIDE + m] = p;
                if (n == 0 && m >= 1)
                    atomicAdd(&gattn[(size_t)b * (NT - 1) + (m - 1)],
                              p * (1.f / H_));
            }
        }
        __syncwarp();

        // PV: lane handles output elems e0, e0+1
        const int e0 = lane * 2;
        float a0 = 0.f, a1 = 0.f;
        for (int m = 0; m < NT; m++) {
            float  p = S[w * S_STRIDE + m];
            float2 v = *(const float2*)&V_s[m * KV_STRIDE + e0];
            a0 += p * v.x;
            a1 += p * v.y;
        }
        float* op = attn_out + (size_t)(b * NT + n) * C_ + h * HD + e0;
        op[0] = a0;
        op[1] = a1;
        __syncwarp();
    }
}

// ---------------------------------------------------------------------------
extern "C" void kernel_launch(void* const* d_in, const int* in_sizes, int n_in,
                              void* d_out, int out_size)
{
    const float* x      = (const float*)d_in[0];   // [64,197,768]
    const float* w_qkv  = (const float*)d_in[1];   // [2304,768]
    const float* w_proj = (const float*)d_in[2];   // [768,768]
    const float* b_proj = (const float*)d_in[3];   // [768]

    float* out   = (float*)d_out;                          // [B,N,C]
    float* gattn = out + (size_t)MROWS * C_;               // [B, N-1]

    float *qkv, *att;
    cudaGetSymbolAddress((void**)&qkv, g_qkv);
    cudaGetSymbolAddress((void**)&att, g_att);

    cudaFuncSetAttribute(attn_kernel,
                         cudaFuncAttributeMaxDynamicSharedMemorySize,
                         ATTN_SMEM_BYTES);

    // zero the global_attn region (accumulated via atomicAdd)
    cudaMemsetAsync(gattn, 0, (size_t)B_ * (NT - 1) * sizeof(float));

    // 1) QKV GEMM: [12608,768] x [2304,768]^T -> [12608,2304]
    sgemm_nt<<<dim3(QKVC / 128, MROWS / 64), 256>>>(
        x, w_qkv, nullptr, qkv, MROWS, QKVC, C_);

    // 2) Attention per (b,h)
    attn_kernel<<<B_ * H_, 256, ATTN_SMEM_BYTES>>>(qkv, att, gattn);

    // 3) Projection GEMM: [12608,768] x [768,768]^T + bias -> [12608,768]
    sgemm_nt<<<dim3(C_ / 128, MROWS / 64), 256>>>(
        att, w_proj, b_proj, out, MROWS, C_, C_);
}

// round 3
// speedup vs baseline: 1.1185x; 1.1185x over previous
#include <cuda_runtime.h>
#include <math.h>

// Problem constants
#define B_    64
#define NT    197
#define C_    768
#define H_    12
#define HD    64
#define MROWS (B_ * NT)     // 12608
#define QKVC  (3 * C_)      // 2304

// Scratch (static device globals — no runtime allocation allowed)
__device__ float g_qkv[(size_t)MROWS * QKVC];   // [B*N, 3C]  q|k|v per row
__device__ float g_att[(size_t)MROWS * C_];     // [B*N, C]   attention output

// ===========================================================================
// 3xTF32 GEMM:  C[m,n] = sum_k A[m,k]*B[n,k] (+ bias[n])    (C = A * B^T)
// Split each fp32 into tf32 hi + tf32 lo; accumulate hi*hi + hi*lo + lo*hi
// with mma.sync.m16n8k8 tf32 -> fp32-comparable accuracy on tensor pipe.
// Block tile 128x128x16, 256 threads (8 warps, 2x4), warp tile 64x32.
// N % 128 == 0 and K % 16 == 0 required; M guarded (clamp loads, pred stores).
// ===========================================================================
#define BM 128
#define BN 128
#define BK 16
#define LDT 132   // padded row length for [k][m] smem tiles (conflict-free)

__device__ __forceinline__ void split_tf32(float x, unsigned& hi, unsigned& lo)
{
    unsigned h;
    asm("cvt.rna.tf32.f32 %0, %1;" : "=r"(h) : "f"(x));
    float l = x - __uint_as_float(h);
    unsigned lu;
    asm("cvt.rna.tf32.f32 %0, %1;" : "=r"(lu) : "f"(l));
    hi = h; lo = lu;
}

__device__ __forceinline__ void mma_tf32(float* c, const unsigned* a, const unsigned* b)
{
    asm volatile(
        "mma.sync.aligned.m16n8k8.row.col.f32.tf32.tf32.f32 "
        "{%0,%1,%2,%3},{%4,%5,%6,%7},{%8,%9},{%0,%1,%2,%3};"
        : "+f"(c[0]), "+f"(c[1]), "+f"(c[2]), "+f"(c[3])
        : "r"(a[0]), "r"(a[1]), "r"(a[2]), "r"(a[3]), "r"(b[0]), "r"(b[1]));
}

__global__ void __launch_bounds__(256) gemm_3xtf32(
    const float* __restrict__ A, const float* __restrict__ Bm,
    const float* __restrict__ bias, float* __restrict__ Cm,
    int M, int N, int K)
{
    __shared__ unsigned As_hi[BK][LDT], As_lo[BK][LDT];
    __shared__ unsigned Bs_hi[BK][LDT], Bs_lo[BK][LDT];

    const int tid    = threadIdx.x;
    const int lane   = tid & 31;
    const int wid    = tid >> 5;
    const int warp_m = wid >> 2;       // 0..1
    const int warp_n = wid & 3;        // 0..3
    const int g      = lane >> 2;      // group 0..7
    const int t      = lane & 3;       // 0..3

    const int lr = tid >> 2;           // 0..63  (load row within half-tile)
    const int lc = (tid & 3) * 4;      // 0,4,8,12 (k offset)

    const int bm = blockIdx.y * BM;
    const int bn = blockIdx.x * BN;

    float acc[4][4][4];
#pragma unroll
    for (int mi = 0; mi < 4; mi++)
#pragma unroll
        for (int ni = 0; ni < 4; ni++)
#pragma unroll
            for (int r = 0; r < 4; r++) acc[mi][ni][r] = 0.f;

    float4 pa0, pa1, pb0, pb1;
    {
        int ra0 = min(bm + lr,      M - 1);
        int ra1 = min(bm + lr + 64, M - 1);
        pa0 = *(const float4*)(A  + (size_t)ra0 * K + lc);
        pa1 = *(const float4*)(A  + (size_t)ra1 * K + lc);
        pb0 = *(const float4*)(Bm + (size_t)(bn + lr)      * K + lc);
        pb1 = *(const float4*)(Bm + (size_t)(bn + lr + 64) * K + lc);
    }

    for (int k0 = 0; k0 < K; k0 += BK) {
        // ---- store current tile to smem with tf32 hi/lo split ----
        {
            const float* va = (const float*)&pa0;
            const float* vb = (const float*)&pb0;
            const float* va2 = (const float*)&pa1;
            const float* vb2 = (const float*)&pb1;
#pragma unroll
            for (int j = 0; j < 4; j++) {
                unsigned h, l;
                split_tf32(va[j], h, l);
                As_hi[lc + j][lr] = h; As_lo[lc + j][lr] = l;
                split_tf32(va2[j], h, l);
                As_hi[lc + j][lr + 64] = h; As_lo[lc + j][lr + 64] = l;
                split_tf32(vb[j], h, l);
                Bs_hi[lc + j][lr] = h; Bs_lo[lc + j][lr] = l;
                split_tf32(vb2[j], h, l);
                Bs_hi[lc + j][lr + 64] = h; Bs_lo[lc + j][lr + 64] = l;
            }
        }
        __syncthreads();

        // ---- prefetch next tile ----
        if (k0 + BK < K) {
            int kn = k0 + BK;
            int ra0 = min(bm + lr,      M - 1);
            int ra1 = min(bm + lr + 64, M - 1);
            pa0 = *(const float4*)(A  + (size_t)ra0 * K + kn + lc);
            pa1 = *(const float4*)(A  + (size_t)ra1 * K + kn + lc);
            pb0 = *(const float4*)(Bm + (size_t)(bn + lr)      * K + kn + lc);
            pb1 = *(const float4*)(Bm + (size_t)(bn + lr + 64) * K + kn + lc);
        }

        // ---- compute: 2 k8 steps ----
#pragma unroll
        for (int ks = 0; ks < BK; ks += 8) {
            unsigned ahi[4][4], alo[4][4];
#pragma unroll
            for (int mi = 0; mi < 4; mi++) {
                int mb = warp_m * 64 + mi * 16 + g;
                int kk = ks + t;
                ahi[mi][0] = As_hi[kk][mb];     ahi[mi][1] = As_hi[kk][mb + 8];
                ahi[mi][2] = As_hi[kk + 4][mb]; ahi[mi][3] = As_hi[kk + 4][mb + 8];
                alo[mi][0] = As_lo[kk][mb];     alo[mi][1] = As_lo[kk][mb + 8];
                alo[mi][2] = As_lo[kk + 4][mb]; alo[mi][3] = As_lo[kk + 4][mb + 8];
            }
            unsigned bhi[4][2], blo[4][2];
#pragma unroll
            for (int ni = 0; ni < 4; ni++) {
                int nb = warp_n * 32 + ni * 8 + g;
                bhi[ni][0] = Bs_hi[ks + t][nb];
                bhi[ni][1] = Bs_hi[ks + 4 + t][nb];
                blo[ni][0] = Bs_lo[ks + t][nb];
                blo[ni][1] = Bs_lo[ks + 4 + t][nb];
            }
#pragma unroll
            for (int mi = 0; mi < 4; mi++)
#pragma unroll
                for (int ni = 0; ni < 4; ni++) {
                    mma_tf32(acc[mi][ni], alo[mi], bhi[ni]);
                    mma_tf32(acc[mi][ni], ahi[mi], blo[ni]);
                    mma_tf32(acc[mi][ni], ahi[mi], bhi[ni]);
                }
        }
        __syncthreads();
    }

    // ---- epilogue ----
#pragma unroll
    for (int ni = 0; ni < 4; ni++) {
        int col = bn + warp_n * 32 + ni * 8 + t * 2;
        float b0 = bias ? bias[col]     : 0.f;
        float b1 = bias ? bias[col + 1] : 0.f;
#pragma unroll
        for (int mi = 0; mi < 4; mi++) {
            int row = bm + warp_m * 64 + mi * 16 + g;
            if (row < M) {
                float2 v0 = make_float2(acc[mi][ni][0] + b0, acc[mi][ni][1] + b1);
                *(float2*)(Cm + (size_t)row * N + col) = v0;
            }
            if (row + 8 < M) {
                float2 v1 = make_float2(acc[mi][ni][2] + b0, acc[mi][ni][3] + b1);
                *(float2*)(Cm + (size_t)(row + 8) * N + col) = v1;
            }
        }
    }
}

// ---------------------------------------------------------------------------
// Attention: one CTA per (b,h). K/V staged in smem (stride 68 -> conflict-free
// float4 QK / float2 PV). Each warp processes query rows n = warp, warp+8, ...
// ---------------------------------------------------------------------------
#define KV_STRIDE 68
#define S_STRIDE  200
#define ATTN_SMEM_FLOATS (2 * NT * KV_STRIDE + 8 * S_STRIDE + 8 * 64)
#define ATTN_SMEM_BYTES  (ATTN_SMEM_FLOATS * 4)

__global__ void __launch_bounds__(256) attn_kernel(
    const float* __restrict__ qkv, float* __restrict__ attn_out,
    float* __restrict__ gattn)
{
    const int b = blockIdx.x / H_;
    const int h = blockIdx.x % H_;

    extern __shared__ float sm[];
    float* K_s = sm;
    float* V_s = K_s + NT * KV_STRIDE;
    float* S   = V_s + NT * KV_STRIDE;   // [8][S_STRIDE]
    float* Qs  = S + 8 * S_STRIDE;       // [8][64]

    const int tid  = threadIdx.x;
    const int lane = tid & 31;
    const int w    = tid >> 5;

    const float* base = qkv + (size_t)b * NT * QKVC + h * HD;

    for (int idx = tid; idx < NT * HD; idx += 256) {
        int m = idx >> 6, e = idx & 63;
        const float* row = base + (size_t)m * QKVC;
        K_s[m * KV_STRIDE + e] = row[C_ + e];
        V_s[m * KV_STRIDE + e] = row[2 * C_ + e];
    }
    __syncthreads();

    const float scale = 0.125f;

    for (int n = w; n < NT; n += 8) {
        const float* qrow = base + (size_t)n * QKVC;
        Qs[w * 64 + lane]      = qrow[lane];
        Qs[w * 64 + lane + 32] = qrow[lane + 32];
        __syncwarp();

        float s[7];
#pragma unroll
        for (int i = 0; i < 7; i++) s[i] = 0.f;
#pragma unroll
        for (int e = 0; e < 64; e += 4) {
            float4 q4 = *(const float4*)&Qs[w * 64 + e];
#pragma unroll
            for (int i = 0; i < 7; i++) {
                int m = lane + 32 * i;
                if (m < NT) {
                    float4 k4 = *(const float4*)&K_s[m * KV_STRIDE + e];
                    s[i] += q4.x * k4.x + q4.y * k4.y + q4.z * k4.z + q4.w * k4.w;
                }
            }
        }
        float mx = -INFINITY;
#pragma unroll
        for (int i = 0; i < 7; i++) {
            int m = lane + 32 * i;
            if (m < NT) { s[i] *= scale; mx = fmaxf(mx, s[i]); }
        }
#pragma unroll
        for (int o = 16; o; o >>= 1)
            mx = fmaxf(mx, __shfl_xor_sync(0xffffffffu, mx, o));

        float sum = 0.f;
#pragma unroll
        for (int i = 0; i < 7; i++) {
            int m = lane + 32 * i;
            if (m < NT) { s[i] = __expf(s[i] - mx); sum += s[i]; }
        }
#pragma unroll
        for (int o = 16; o; o >>= 1)
            sum += __shfl_xor_sync(0xffffffffu, sum, o);
        const float inv = 1.f / sum;

#pragma unroll
        for (int i = 0; i < 7; i++) {
            int m = lane + 32 * i;
            if (m < NT) {
                float p = s[i] * inv;
                S[w * S_STRIDE + m] = p;
                if (n == 0 && m >= 1)
                    atomicAdd(&gattn[(size_t)b * (NT - 1) + (m - 1)],
                              p * (1.f / H_));
            }
        }
        __syncwarp();

        const int e0 = lane * 2;
        float a0 = 0.f, a1 = 0.f;
        for (int m = 0; m < NT; m++) {
            float  p = S[w * S_STRIDE + m];
            float2 v = *(const float2*)&V_s[m * KV_STRIDE + e0];
            a0 += p * v.x;
            a1 += p * v.y;
        }
        float* op = attn_out + (size_t)(b * NT + n) * C_ + h * HD + e0;
        op[0] = a0;
        op[1] = a1;
        __syncwarp();
    }
}

// ---------------------------------------------------------------------------
extern "C" void kernel_launch(void* const* d_in, const int* in_sizes, int n_in,
                              void* d_out, int out_size)
{
    const float* x      = (const float*)d_in[0];   // [64,197,768]
    const float* w_qkv  = (const float*)d_in[1];   // [2304,768]
    const float* w_proj = (const float*)d_in[2];   // [768,768]
    const float* b_proj = (const float*)d_in[3];   // [768]

    float* out   = (float*)d_out;                          // [B,N,C]
    float* gattn = out + (size_t)MROWS * C_;               // [B, N-1]

    float *qkv, *att;
    cudaGetSymbolAddress((void**)&qkv, g_qkv);
    cudaGetSymbolAddress((void**)&att, g_att);

    cudaFuncSetAttribute(attn_kernel,
                         cudaFuncAttributeMaxDynamicSharedMemorySize,
                         ATTN_SMEM_BYTES);

    cudaMemsetAsync(gattn, 0, (size_t)B_ * (NT - 1) * sizeof(float));

    // 1) QKV GEMM: [12608,768] x [2304,768]^T -> [12608,2304]
    gemm_3xtf32<<<dim3(QKVC / BN, (MROWS + BM - 1) / BM), 256>>>(
        x, w_qkv, nullptr, qkv, MROWS, QKVC, C_);

    // 2) Attention per (b,h)
    attn_kernel<<<B_ * H_, 256, ATTN_SMEM_BYTES>>>(qkv, att, gattn);

    // 3) Projection GEMM: [12608,768] x [768,768]^T + bias -> [12608,768]
    gemm_3xtf32<<<dim3(C_ / BN, (MROWS + BM - 1) / BM), 256>>>(
        att, w_proj, b_proj, out, MROWS, C_, C_);
}